// round 2
// baseline (speedup 1.0000x reference)
#include <cuda_runtime.h>

#define EMB   2048
#define NBATCH 4
#define LSEQ  2048
#define E4    (EMB / 4)          // 512 float4 per row
#define RGRP  16                 // row groups for Wv column-sum

// Scratch (no device allocation allowed)
__device__ float g_part[RGRP * EMB];     // partial column sums of Wv
__device__ float g_wsum[EMB];            // wsum[e] = sum_d Wv[d][e]
__device__ float g_bsum;                 // sum(bv)
__device__ float g_S[NBATCH * LSEQ];     // S[n][v] = rowsum of v-projection
__device__ float g_T[NBATCH * EMB];      // T[n][e] = Wo @ S[n] + bo

// ---------------------------------------------------------------------------
// K1: partial column sums of Wv. grid (8 col-groups, 16 row-groups) x 256.
// Coalesced: warp reads 32 consecutive floats of one Wv row per step.
// ---------------------------------------------------------------------------
__global__ void k1_partial(const float* __restrict__ Wv) {
    const int e = blockIdx.x * 256 + threadIdx.x;
    const int r = blockIdx.y;
    const float* p = Wv + (size_t)r * (EMB / RGRP) * EMB + e;
    float s = 0.f;
#pragma unroll 8
    for (int d = 0; d < EMB / RGRP; ++d)
        s += p[(size_t)d * EMB];
    g_part[r * EMB + e] = s;
}

// ---------------------------------------------------------------------------
// K1b: reduce the 16 partials -> g_wsum (blocks 0..7); block 8 sums bv.
// Fixed-order reductions -> deterministic.
// ---------------------------------------------------------------------------
__global__ void k1b_reduce(const float* __restrict__ bv) {
    if (blockIdx.x < 8) {
        const int e = blockIdx.x * 256 + threadIdx.x;
        float s = 0.f;
#pragma unroll
        for (int r = 0; r < RGRP; ++r)
            s += g_part[r * EMB + e];
        g_wsum[e] = s;
    } else {
        __shared__ float sh[256];
        float s = 0.f;
        for (int i = threadIdx.x; i < EMB; i += 256)
            s += bv[i];
        sh[threadIdx.x] = s;
        __syncthreads();
        for (int off = 128; off > 0; off >>= 1) {
            if (threadIdx.x < off) sh[threadIdx.x] += sh[threadIdx.x + off];
            __syncthreads();
        }
        if (threadIdx.x == 0) g_bsum = sh[0];
    }
}

// ---------------------------------------------------------------------------
// K2: S[row] = dot(values[row,:], wsum) + bsum.  One block per row (8192).
// float4 vectorized, 2 iterations per thread. 64 MB streaming read.
// ---------------------------------------------------------------------------
__global__ void k2_rowdot(const float* __restrict__ values) {
    const int row = blockIdx.x;
    const float4* v4 = reinterpret_cast<const float4*>(values) + (size_t)row * E4;
    const float4* w4 = reinterpret_cast<const float4*>(g_wsum);
    float s = 0.f;
#pragma unroll
    for (int i = threadIdx.x; i < E4; i += 256) {
        float4 a = v4[i];
        float4 b = w4[i];
        s += a.x * b.x + a.y * b.y + a.z * b.z + a.w * b.w;
    }
    __shared__ float sh[8];
    for (int o = 16; o > 0; o >>= 1)
        s += __shfl_down_sync(0xffffffffu, s, o);
    if ((threadIdx.x & 31) == 0) sh[threadIdx.x >> 5] = s;
    __syncthreads();
    if (threadIdx.x < 8) {
        float t = sh[threadIdx.x];
        for (int o = 4; o > 0; o >>= 1)
            t += __shfl_down_sync(0x000000ffu, t, o);
        if (threadIdx.x == 0) g_S[row] = t + g_bsum;
    }
}

// ---------------------------------------------------------------------------
// K3: T[n][e] = sum_v Wo[e][v] * S[n][v] + bo[e].  One block per e (2048).
// Wo row read ONCE per block, reused for all 4 batches. S is 32KB, L2-hot.
// ---------------------------------------------------------------------------
__global__ void k3_gemv(const float* __restrict__ Wo, const float* __restrict__ bo) {
    const int e = blockIdx.x;
    const float4* w4 = reinterpret_cast<const float4*>(Wo) + (size_t)e * E4;
    const float4* s4 = reinterpret_cast<const float4*>(g_S);
    float a0 = 0.f, a1 = 0.f, a2 = 0.f, a3 = 0.f;
#pragma unroll
    for (int i = threadIdx.x; i < E4; i += 256) {
        float4 w  = w4[i];
        float4 p0 = s4[0 * E4 + i];
        float4 p1 = s4[1 * E4 + i];
        float4 p2 = s4[2 * E4 + i];
        float4 p3 = s4[3 * E4 + i];
        a0 += w.x * p0.x + w.y * p0.y + w.z * p0.z + w.w * p0.w;
        a1 += w.x * p1.x + w.y * p1.y + w.z * p1.z + w.w * p1.w;
        a2 += w.x * p2.x + w.y * p2.y + w.z * p2.z + w.w * p2.w;
        a3 += w.x * p3.x + w.y * p3.y + w.z * p3.z + w.w * p3.w;
    }
    for (int o = 16; o > 0; o >>= 1) {
        a0 += __shfl_down_sync(0xffffffffu, a0, o);
        a1 += __shfl_down_sync(0xffffffffu, a1, o);
        a2 += __shfl_down_sync(0xffffffffu, a2, o);
        a3 += __shfl_down_sync(0xffffffffu, a3, o);
    }
    __shared__ float sh[8][4];
    if ((threadIdx.x & 31) == 0) {
        const int w = threadIdx.x >> 5;
        sh[w][0] = a0; sh[w][1] = a1; sh[w][2] = a2; sh[w][3] = a3;
    }
    __syncthreads();
    if (threadIdx.x < 32) {
        const int n = threadIdx.x >> 3;   // 0..3
        const int w = threadIdx.x & 7;    // 0..7
        float t = sh[w][n];
        for (int o = 4; o > 0; o >>= 1)
            t += __shfl_down_sync(0xffffffffu, t, o);
        if (w == 0) g_T[n * EMB + e] = t + bo[e];
    }
}

// ---------------------------------------------------------------------------
// K4: broadcast write: out[n][q][e] = T[n][e] for all q. 64 MB streaming write,
// one float4 per thread. T4 reads are consecutive per warp -> L1/L2 hits.
// ---------------------------------------------------------------------------
__global__ void k4_bcast(float4* __restrict__ out) {
    const size_t f = (size_t)blockIdx.x * 256 + threadIdx.x;   // 0 .. 4M-1
    const float4* t4 = reinterpret_cast<const float4*>(g_T);
    const int n  = (int)(f >> 20);        // LSEQ * E4 = 1,048,576 per batch
    const int e4 = (int)(f & (E4 - 1));
    out[f] = t4[n * E4 + e4];
}

// ---------------------------------------------------------------------------
extern "C" void kernel_launch(void* const* d_in, const int* /*in_sizes*/, int /*n_in*/,
                              void* d_out, int /*out_size*/) {
    const float* values = (const float*)d_in[0];
    // d_in[1] keys, d_in[2] queries, d_in[5..8] Wk/bk/Wq/bq: provably unused
    const float* Wv = (const float*)d_in[3];
    const float* bv = (const float*)d_in[4];
    const float* Wo = (const float*)d_in[9];
    const float* bo = (const float*)d_in[10];

    k1_partial<<<dim3(8, RGRP), 256>>>(Wv);
    k1b_reduce<<<9, 256>>>(bv);
    k2_rowdot<<<NBATCH * LSEQ, 256>>>(values);
    k3_gemv<<<EMB, 256>>>(Wo, bo);
    k4_bcast<<<(NBATCH * LSEQ * E4) / 256, 256>>>((float4*)d_out);
}

// round 3
// speedup vs baseline: 1.0628x; 1.0628x over previous
#include <cuda_runtime.h>

#define EMB    2048
#define NBATCH 4
#define LSEQ   2048
#define E4     (EMB / 4)          // 512 float4 per row
#define RGRP   16                 // row groups for Wv column-sum

// Scratch (no device allocation allowed)
__device__ float g_part[RGRP * EMB];     // partial column sums of Wv
__device__ float g_wsum[EMB];            // wsum[e] = sum_d Wv[d][e]
__device__ float g_bsum;                 // sum(bv)
__device__ float g_S[NBATCH * LSEQ];     // S[n][v] = rowsum of v-projection
__device__ float g_T[NBATCH * EMB];      // T[n][e] = Wo @ S[n] + bo

// ---------------------------------------------------------------------------
// K1: partial column sums of Wv. grid (8 col-groups, 16 row-groups) x 256.
// Coalesced: warp reads 32 consecutive floats of one Wv row per step;
// 128 independent strided loads per thread -> deep MLP.
// ---------------------------------------------------------------------------
__global__ void k1_partial(const float* __restrict__ Wv) {
    const int e = blockIdx.x * 256 + threadIdx.x;
    const int r = blockIdx.y;
    const float* p = Wv + (size_t)r * (EMB / RGRP) * EMB + e;
    float s0 = 0.f, s1 = 0.f, s2 = 0.f, s3 = 0.f;
#pragma unroll 4
    for (int d = 0; d < EMB / RGRP; d += 4) {
        s0 += p[(size_t)(d + 0) * EMB];
        s1 += p[(size_t)(d + 1) * EMB];
        s2 += p[(size_t)(d + 2) * EMB];
        s3 += p[(size_t)(d + 3) * EMB];
    }
    g_part[r * EMB + e] = (s0 + s1) + (s2 + s3);
}

// ---------------------------------------------------------------------------
// K1b: reduce the 16 partials -> g_wsum (blocks 0..7); block 8 sums bv.
// Fixed-order reductions -> deterministic.
// ---------------------------------------------------------------------------
__global__ void k1b_reduce(const float* __restrict__ bv) {
    if (blockIdx.x < 8) {
        const int e = blockIdx.x * 256 + threadIdx.x;
        float s = 0.f;
#pragma unroll
        for (int r = 0; r < RGRP; ++r)
            s += g_part[r * EMB + e];
        g_wsum[e] = s;
    } else {
        __shared__ float sh[256];
        float s = 0.f;
        for (int i = threadIdx.x; i < EMB; i += 256)
            s += bv[i];
        sh[threadIdx.x] = s;
        __syncthreads();
        for (int off = 128; off > 0; off >>= 1) {
            if (threadIdx.x < off) sh[threadIdx.x] += sh[threadIdx.x + off];
            __syncthreads();
        }
        if (threadIdx.x == 0) g_bsum = sh[0];
    }
}

// ---------------------------------------------------------------------------
// K2: S[row] = dot(values[row,:], wsum) + bsum.  ONE WARP per row.
// 8192 warps; each lane does 16 independent float4 loads -> MLP 16.
// wsum (8 KB) is L1-resident after first touch. 64 MB streaming read.
// ---------------------------------------------------------------------------
__global__ void k2_rowdot(const float* __restrict__ values) {
    const int warp = (blockIdx.x * blockDim.x + threadIdx.x) >> 5;  // 0..8191
    const int lane = threadIdx.x & 31;
    const float4* v4 = reinterpret_cast<const float4*>(values) + (size_t)warp * E4;
    const float4* w4 = reinterpret_cast<const float4*>(g_wsum);
    float s = 0.f;
#pragma unroll
    for (int i = lane; i < E4; i += 32) {
        float4 a = v4[i];
        float4 b = w4[i];
        s += a.x * b.x + a.y * b.y + a.z * b.z + a.w * b.w;
    }
#pragma unroll
    for (int o = 16; o > 0; o >>= 1)
        s += __shfl_down_sync(0xffffffffu, s, o);
    if (lane == 0) g_S[warp] = s + g_bsum;
}

// ---------------------------------------------------------------------------
// K3: T[n][e] = sum_v Wo[e][v] * S[n][v] + bo[e].  ONE WARP per e row.
// 2048 warps; 16 independent Wo float4 loads per lane; S (32 KB) is L2/L1-hot
// and amortized across 4 batch accumulators.
// ---------------------------------------------------------------------------
__global__ void k3_gemv(const float* __restrict__ Wo, const float* __restrict__ bo) {
    const int e    = (blockIdx.x * blockDim.x + threadIdx.x) >> 5;  // 0..2047
    const int lane = threadIdx.x & 31;
    const float4* w4 = reinterpret_cast<const float4*>(Wo) + (size_t)e * E4;
    const float4* s4 = reinterpret_cast<const float4*>(g_S);
    float a0 = 0.f, a1 = 0.f, a2 = 0.f, a3 = 0.f;
#pragma unroll
    for (int i = lane; i < E4; i += 32) {
        float4 w  = w4[i];
        float4 p0 = s4[0 * E4 + i];
        float4 p1 = s4[1 * E4 + i];
        float4 p2 = s4[2 * E4 + i];
        float4 p3 = s4[3 * E4 + i];
        a0 += w.x * p0.x + w.y * p0.y + w.z * p0.z + w.w * p0.w;
        a1 += w.x * p1.x + w.y * p1.y + w.z * p1.z + w.w * p1.w;
        a2 += w.x * p2.x + w.y * p2.y + w.z * p2.z + w.w * p2.w;
        a3 += w.x * p3.x + w.y * p3.y + w.z * p3.z + w.w * p3.w;
    }
#pragma unroll
    for (int o = 16; o > 0; o >>= 1) {
        a0 += __shfl_down_sync(0xffffffffu, a0, o);
        a1 += __shfl_down_sync(0xffffffffu, a1, o);
        a2 += __shfl_down_sync(0xffffffffu, a2, o);
        a3 += __shfl_down_sync(0xffffffffu, a3, o);
    }
    if (lane == 0) {
        const float b = bo[e];
        g_T[0 * EMB + e] = a0 + b;
        g_T[1 * EMB + e] = a1 + b;
        g_T[2 * EMB + e] = a2 + b;
        g_T[3 * EMB + e] = a3 + b;
    }
}

// ---------------------------------------------------------------------------
// K4: broadcast write: out[n][q][e] = T[n][e] for all q.
// Each thread loads one T float4 (L1-hot) and writes it to 4 q positions.
// Consecutive lanes hit consecutive e4 -> every store fully coalesced.
// 64 MB streaming write.
// ---------------------------------------------------------------------------
__global__ void k4_bcast(float4* __restrict__ out) {
    const size_t idx = (size_t)blockIdx.x * 256 + threadIdx.x;   // 0 .. 1M-1
    const float4* t4 = reinterpret_cast<const float4*>(g_T);
    const int n   = (int)(idx >> 18);          // (LSEQ/4)*E4 = 262144 per batch
    const int rem = (int)(idx & 262143);
    const int q4  = rem >> 9;                  // group of 4 q rows
    const int e4  = rem & (E4 - 1);
    const float4 t = t4[n * E4 + e4];
    size_t base = (((size_t)n * LSEQ) + (size_t)q4 * 4) * E4 + e4;
    out[base]           = t;
    out[base + 1 * E4]  = t;
    out[base + 2 * E4]  = t;
    out[base + 3 * E4]  = t;
}

// ---------------------------------------------------------------------------
extern "C" void kernel_launch(void* const* d_in, const int* /*in_sizes*/, int /*n_in*/,
                              void* d_out, int /*out_size*/) {
    const float* values = (const float*)d_in[0];
    // d_in[1] keys, d_in[2] queries, d_in[5..8] Wk/bk/Wq/bq: provably unused
    // (softmax row-sums are exactly 1, and the "nqk,nvd->nqv" einsum decouples)
    const float* Wv = (const float*)d_in[3];
    const float* bv = (const float*)d_in[4];
    const float* Wo = (const float*)d_in[9];
    const float* bo = (const float*)d_in[10];

    k1_partial<<<dim3(8, RGRP), 256>>>(Wv);
    k1b_reduce<<<9, 256>>>(bv);
    k2_rowdot<<<(NBATCH * LSEQ * 32) / 256, 256>>>(values);   // 1024 blocks
    k3_gemv  <<<(EMB * 32) / 256, 256>>>(Wo, bo);             // 256 blocks
    k4_bcast <<<(NBATCH * LSEQ * E4 / 4) / 256, 256>>>((float4*)d_out); // 4096 blocks
}

// round 4
// speedup vs baseline: 1.0763x; 1.0127x over previous
#include <cuda_runtime.h>

#define EMB    2048
#define NBATCH 4
#define LSEQ   2048
#define E4     (EMB / 4)          // 512 float4 per row
#define RGRP   16                 // row groups for Wv column-sum

// Scratch (no device allocation allowed)
__device__ float g_part[RGRP * EMB];     // partial column sums of Wv
__device__ float g_wsum[EMB];            // wsum[e] = sum_d Wv[d][e]
__device__ float g_bsum;                 // sum(bv)
__device__ float g_S[NBATCH * LSEQ];     // S[n][v] = rowsum of v-projection
__device__ float g_T[NBATCH * EMB];      // T[n][e] = Wo @ S[n] + bo

// ---------------------------------------------------------------------------
// K1: partial column sums of Wv. grid (8 col-groups, 16 row-groups) x 256.
// Coalesced: warp reads 32 consecutive floats of one Wv row per step;
// 4 independent accumulator streams -> deep MLP.
// ---------------------------------------------------------------------------
__global__ void k1_partial(const float* __restrict__ Wv) {
    const int e = blockIdx.x * 256 + threadIdx.x;
    const int r = blockIdx.y;
    const float* p = Wv + (size_t)r * (EMB / RGRP) * EMB + e;
    float s0 = 0.f, s1 = 0.f, s2 = 0.f, s3 = 0.f;
#pragma unroll 4
    for (int d = 0; d < EMB / RGRP; d += 4) {
        s0 += p[(size_t)(d + 0) * EMB];
        s1 += p[(size_t)(d + 1) * EMB];
        s2 += p[(size_t)(d + 2) * EMB];
        s3 += p[(size_t)(d + 3) * EMB];
    }
    g_part[r * EMB + e] = (s0 + s1) + (s2 + s3);
}

// ---------------------------------------------------------------------------
// K1b: reduce the 16 partials -> g_wsum (blocks 0..7); block 8 sums bv.
// Fixed-order reductions -> deterministic.
// ---------------------------------------------------------------------------
__global__ void k1b_reduce(const float* __restrict__ bv) {
    if (blockIdx.x < 8) {
        const int e = blockIdx.x * 256 + threadIdx.x;
        float s = 0.f;
#pragma unroll
        for (int r = 0; r < RGRP; ++r)
            s += g_part[r * EMB + e];
        g_wsum[e] = s;
    } else {
        __shared__ float sh[256];
        float s = 0.f;
        for (int i = threadIdx.x; i < EMB; i += 256)
            s += bv[i];
        sh[threadIdx.x] = s;
        __syncthreads();
        for (int off = 128; off > 0; off >>= 1) {
            if (threadIdx.x < off) sh[threadIdx.x] += sh[threadIdx.x + off];
            __syncthreads();
        }
        if (threadIdx.x == 0) g_bsum = sh[0];
    }
}

// ---------------------------------------------------------------------------
// K2: S[row] = dot(values[row,:], wsum) + bsum.  ONE WARP per row.
// 8192 warps; each lane does 16 independent float4 loads -> MLP 16.
// wsum lives in smem (one 8KB copy per block). 64 MB streaming read.
// ---------------------------------------------------------------------------
__global__ void k2_rowdot(const float* __restrict__ values) {
    __shared__ float4 sw[E4];                       // 8 KB wsum copy
    {
        const float4* w4 = reinterpret_cast<const float4*>(g_wsum);
        for (int i = threadIdx.x; i < E4; i += 256)
            sw[i] = w4[i];
    }
    __syncthreads();

    const int warp = (blockIdx.x * blockDim.x + threadIdx.x) >> 5;  // 0..8191
    const int lane = threadIdx.x & 31;
    const float4* v4 = reinterpret_cast<const float4*>(values) + (size_t)warp * E4;
    float s = 0.f;
#pragma unroll
    for (int i = lane; i < E4; i += 32) {
        float4 a = v4[i];
        float4 b = sw[i];
        s += a.x * b.x + a.y * b.y + a.z * b.z + a.w * b.w;
    }
#pragma unroll
    for (int o = 16; o > 0; o >>= 1)
        s += __shfl_down_sync(0xffffffffu, s, o);
    if (lane == 0) g_S[warp] = s + g_bsum;
}

// ---------------------------------------------------------------------------
// K3: T[n][e] = sum_v Wo[e][v] * S[n][v] + bo[e].
// Block = 8 warps = 8 e-rows. S (32 KB) staged in smem ONCE per block,
// then each warp streams its Wo row from DRAM (16 independent float4
// loads per lane, MLP 16) against smem-resident S. S L2 traffic: 8 MB
// instead of 64 MB -> kernel is a pure 16 MB Wo stream.
// ---------------------------------------------------------------------------
__global__ void k3_gemv(const float* __restrict__ Wo, const float* __restrict__ bo) {
    __shared__ float4 sS[NBATCH * E4];              // 32 KB
    {
        const float4* s4 = reinterpret_cast<const float4*>(g_S);
        for (int i = threadIdx.x; i < NBATCH * E4; i += 256)
            sS[i] = s4[i];
    }
    __syncthreads();

    const int warp = threadIdx.x >> 5;              // 0..7
    const int lane = threadIdx.x & 31;
    const int e    = blockIdx.x * 8 + warp;         // 0..2047
    const float4* w4 = reinterpret_cast<const float4*>(Wo) + (size_t)e * E4;

    float a0 = 0.f, a1 = 0.f, a2 = 0.f, a3 = 0.f;
#pragma unroll
    for (int i = lane; i < E4; i += 32) {
        float4 w  = w4[i];
        float4 p0 = sS[0 * E4 + i];
        float4 p1 = sS[1 * E4 + i];
        float4 p2 = sS[2 * E4 + i];
        float4 p3 = sS[3 * E4 + i];
        a0 += w.x * p0.x + w.y * p0.y + w.z * p0.z + w.w * p0.w;
        a1 += w.x * p1.x + w.y * p1.y + w.z * p1.z + w.w * p1.w;
        a2 += w.x * p2.x + w.y * p2.y + w.z * p2.z + w.w * p2.w;
        a3 += w.x * p3.x + w.y * p3.y + w.z * p3.z + w.w * p3.w;
    }
#pragma unroll
    for (int o = 16; o > 0; o >>= 1) {
        a0 += __shfl_down_sync(0xffffffffu, a0, o);
        a1 += __shfl_down_sync(0xffffffffu, a1, o);
        a2 += __shfl_down_sync(0xffffffffu, a2, o);
        a3 += __shfl_down_sync(0xffffffffu, a3, o);
    }
    if (lane == 0) {
        const float b = bo[e];
        g_T[0 * EMB + e] = a0 + b;
        g_T[1 * EMB + e] = a1 + b;
        g_T[2 * EMB + e] = a2 + b;
        g_T[3 * EMB + e] = a3 + b;
    }
}

// ---------------------------------------------------------------------------
// K4: broadcast write: out[n][q][e] = T[n][e] for all q.
// Each thread loads one T float4 (L1-hot) and writes it to 4 q positions.
// Consecutive lanes hit consecutive e4 -> every store fully coalesced.
// 64 MB streaming write.
// ---------------------------------------------------------------------------
__global__ void k4_bcast(float4* __restrict__ out) {
    const size_t idx = (size_t)blockIdx.x * 256 + threadIdx.x;   // 0 .. 1M-1
    const float4* t4 = reinterpret_cast<const float4*>(g_T);
    const int n   = (int)(idx >> 18);          // (LSEQ/4)*E4 = 262144 per batch
    const int rem = (int)(idx & 262143);
    const int q4  = rem >> 9;                  // group of 4 q rows
    const int e4  = rem & (E4 - 1);
    const float4 t = t4[n * E4 + e4];
    size_t base = (((size_t)n * LSEQ) + (size_t)q4 * 4) * E4 + e4;
    out[base]           = t;
    out[base + 1 * E4]  = t;
    out[base + 2 * E4]  = t;
    out[base + 3 * E4]  = t;
}

// ---------------------------------------------------------------------------
extern "C" void kernel_launch(void* const* d_in, const int* /*in_sizes*/, int /*n_in*/,
                              void* d_out, int /*out_size*/) {
    const float* values = (const float*)d_in[0];
    // d_in[1] keys, d_in[2] queries, d_in[5..8] Wk/bk/Wq/bq: provably unused
    // (softmax row-sums are exactly 1, and the "nqk,nvd->nqv" einsum decouples)
    const float* Wv = (const float*)d_in[3];
    const float* bv = (const float*)d_in[4];
    const float* Wo = (const float*)d_in[9];
    const float* bo = (const float*)d_in[10];

    k1_partial<<<dim3(8, RGRP), 256>>>(Wv);
    k1b_reduce<<<9, 256>>>(bv);
    k2_rowdot<<<(NBATCH * LSEQ * 32) / 256, 256>>>(values);   // 1024 blocks
    k3_gemv  <<<EMB / 8, 256>>>(Wo, bo);                      // 256 blocks
    k4_bcast <<<(NBATCH * LSEQ * E4 / 4) / 256, 256>>>((float4*)d_out); // 4096 blocks
}

// round 5
// speedup vs baseline: 1.1084x; 1.0298x over previous
#include <cuda_runtime.h>

#define EMB    2048
#define NBATCH 4
#define LSEQ   2048
#define E4     (EMB / 4)          // 512 float4 per row
#define RGRP   16                 // row groups for Wv column-sum

// Scratch (no device allocation allowed)
__device__ float g_part[RGRP * EMB];     // partial column sums of Wv
__device__ float g_wsum[EMB];            // wsum[e] = sum_d Wv[d][e]
__device__ float g_bsum;                 // sum(bv)
__device__ float g_S[NBATCH * LSEQ];     // S[n][v] = rowsum of v-projection
__device__ float g_T[NBATCH * EMB];      // T[n][e] = Wo @ S[n] + bo

// ---------------------------------------------------------------------------
// K1: partial column sums of Wv. grid (8 col-groups, 16 row-groups) x 256.
// Coalesced: warp reads 32 consecutive floats of one Wv row per step;
// 4 independent accumulator streams -> deep MLP.
// ---------------------------------------------------------------------------
__global__ void k1_partial(const float* __restrict__ Wv) {
    const int e = blockIdx.x * 256 + threadIdx.x;
    const int r = blockIdx.y;
    const float* p = Wv + (size_t)r * (EMB / RGRP) * EMB + e;
    float s0 = 0.f, s1 = 0.f, s2 = 0.f, s3 = 0.f;
#pragma unroll 4
    for (int d = 0; d < EMB / RGRP; d += 4) {
        s0 += p[(size_t)(d + 0) * EMB];
        s1 += p[(size_t)(d + 1) * EMB];
        s2 += p[(size_t)(d + 2) * EMB];
        s3 += p[(size_t)(d + 3) * EMB];
    }
    g_part[r * EMB + e] = (s0 + s1) + (s2 + s3);
}

// ---------------------------------------------------------------------------
// K1b: reduce the 16 partials -> g_wsum (blocks 0..7); block 8 sums bv.
// Fixed-order reductions -> deterministic.
// ---------------------------------------------------------------------------
__global__ void k1b_reduce(const float* __restrict__ bv) {
    if (blockIdx.x < 8) {
        const int e = blockIdx.x * 256 + threadIdx.x;
        float s = 0.f;
#pragma unroll
        for (int r = 0; r < RGRP; ++r)
            s += g_part[r * EMB + e];
        g_wsum[e] = s;
    } else {
        __shared__ float sh[256];
        float s = 0.f;
        for (int i = threadIdx.x; i < EMB; i += 256)
            s += bv[i];
        sh[threadIdx.x] = s;
        __syncthreads();
        for (int off = 128; off > 0; off >>= 1) {
            if (threadIdx.x < off) sh[threadIdx.x] += sh[threadIdx.x + off];
            __syncthreads();
        }
        if (threadIdx.x == 0) g_bsum = sh[0];
    }
}

// ---------------------------------------------------------------------------
// K2: S[row] = dot(values[row,:], wsum) + bsum.  ONE WARP per row.
// 8192 warps; each lane does 16 independent float4 loads -> MLP 16.
// wsum lives in smem (one 8KB copy per block). 64 MB streaming read.
// ---------------------------------------------------------------------------
__global__ void k2_rowdot(const float* __restrict__ values) {
    __shared__ float4 sw[E4];                       // 8 KB wsum copy
    {
        const float4* w4 = reinterpret_cast<const float4*>(g_wsum);
        for (int i = threadIdx.x; i < E4; i += 256)
            sw[i] = w4[i];
    }
    __syncthreads();

    const int warp = (blockIdx.x * blockDim.x + threadIdx.x) >> 5;  // 0..8191
    const int lane = threadIdx.x & 31;
    const float4* v4 = reinterpret_cast<const float4*>(values) + (size_t)warp * E4;
    float s = 0.f;
#pragma unroll
    for (int i = lane; i < E4; i += 32) {
        float4 a = v4[i];
        float4 b = sw[i];
        s += a.x * b.x + a.y * b.y + a.z * b.z + a.w * b.w;
    }
#pragma unroll
    for (int o = 16; o > 0; o >>= 1)
        s += __shfl_down_sync(0xffffffffu, s, o);
    if (lane == 0) g_S[warp] = s + g_bsum;
}

// ---------------------------------------------------------------------------
// K3: T[n][e] = sum_v Wo[e][v] * S[n][v] + bo[e].
// Block = 8 warps = 8 e-rows. S (32 KB) staged in smem ONCE per block,
// then each warp streams its Wo row from DRAM (16 independent float4
// loads per lane, MLP 16) against smem-resident S. S L2 traffic: 8 MB
// instead of 64 MB -> kernel is a pure 16 MB Wo stream.
// ---------------------------------------------------------------------------
__global__ void k3_gemv(const float* __restrict__ Wo, const float* __restrict__ bo) {
    __shared__ float4 sS[NBATCH * E4];              // 32 KB
    {
        const float4* s4 = reinterpret_cast<const float4*>(g_S);
        for (int i = threadIdx.x; i < NBATCH * E4; i += 256)
            sS[i] = s4[i];
    }
    __syncthreads();

    const int warp = threadIdx.x >> 5;              // 0..7
    const int lane = threadIdx.x & 31;
    const int e    = blockIdx.x * 8 + warp;         // 0..2047
    const float4* w4 = reinterpret_cast<const float4*>(Wo) + (size_t)e * E4;

    float a0 = 0.f, a1 = 0.f, a2 = 0.f, a3 = 0.f;
#pragma unroll
    for (int i = lane; i < E4; i += 32) {
        float4 w  = w4[i];
        float4 p0 = sS[0 * E4 + i];
        float4 p1 = sS[1 * E4 + i];
        float4 p2 = sS[2 * E4 + i];
        float4 p3 = sS[3 * E4 + i];
        a0 += w.x * p0.x + w.y * p0.y + w.z * p0.z + w.w * p0.w;
        a1 += w.x * p1.x + w.y * p1.y + w.z * p1.z + w.w * p1.w;
        a2 += w.x * p2.x + w.y * p2.y + w.z * p2.z + w.w * p2.w;
        a3 += w.x * p3.x + w.y * p3.y + w.z * p3.z + w.w * p3.w;
    }
#pragma unroll
    for (int o = 16; o > 0; o >>= 1) {
        a0 += __shfl_down_sync(0xffffffffu, a0, o);
        a1 += __shfl_down_sync(0xffffffffu, a1, o);
        a2 += __shfl_down_sync(0xffffffffu, a2, o);
        a3 += __shfl_down_sync(0xffffffffu, a3, o);
    }
    if (lane == 0) {
        const float b = bo[e];
        g_T[0 * EMB + e] = a0 + b;
        g_T[1 * EMB + e] = a1 + b;
        g_T[2 * EMB + e] = a2 + b;
        g_T[3 * EMB + e] = a3 + b;
    }
}

// ---------------------------------------------------------------------------
// K4: broadcast write: out[n][q][e] = T[n][e] for all q.
// Each thread loads one T float4 (L1-hot) and writes it to 4 q positions.
// Consecutive lanes hit consecutive e4 -> every store fully coalesced.
// 64 MB streaming write.
// ---------------------------------------------------------------------------
__global__ void k4_bcast(float4* __restrict__ out) {
    const size_t idx = (size_t)blockIdx.x * 256 + threadIdx.x;   // 0 .. 1M-1
    const float4* t4 = reinterpret_cast<const float4*>(g_T);
    const int n   = (int)(idx >> 18);          // (LSEQ/4)*E4 = 262144 per batch
    const int rem = (int)(idx & 262143);
    const int q4  = rem >> 9;                  // group of 4 q rows
    const int e4  = rem & (E4 - 1);
    const float4 t = t4[n * E4 + e4];
    size_t base = (((size_t)n * LSEQ) + (size_t)q4 * 4) * E4 + e4;
    out[base]           = t;
    out[base + 1 * E4]  = t;
    out[base + 2 * E4]  = t;
    out[base + 3 * E4]  = t;
}

// ---------------------------------------------------------------------------
extern "C" void kernel_launch(void* const* d_in, const int* /*in_sizes*/, int /*n_in*/,
                              void* d_out, int /*out_size*/) {
    const float* values = (const float*)d_in[0];
    // d_in[1] keys, d_in[2] queries, d_in[5..8] Wk/bk/Wq/bq: provably unused
    // (softmax row-sums are exactly 1, and the "nqk,nvd->nqv" einsum decouples)
    const float* Wv = (const float*)d_in[3];
    const float* bv = (const float*)d_in[4];
    const float* Wo = (const float*)d_in[9];
    const float* bo = (const float*)d_in[10];

    k1_partial<<<dim3(8, RGRP), 256>>>(Wv);
    k1b_reduce<<<9, 256>>>(bv);
    k2_rowdot<<<(NBATCH * LSEQ * 32) / 256, 256>>>(values);   // 1024 blocks
    k3_gemv  <<<EMB / 8, 256>>>(Wo, bo);                      // 256 blocks
    k4_bcast <<<(NBATCH * LSEQ * E4 / 4) / 256, 256>>>((float4*)d_out); // 4096 blocks
}